// round 12
// baseline (speedup 1.0000x reference)
#include <cuda_runtime.h>

#define NA 256
#define NB 512
#define CMAX 0.05f
#define NITERS 300
#define PITERS 30
#define QUADROUNDS 3
#define NEWTONROUNDS 6

typedef unsigned long long ull;

// Upper-triangular Q blocks, fp32: 512 batches * 10 blocks * 64*64 floats = 82 MB
__device__ float g_Qs[(size_t)NB * 10 * 4096];

// gj-grouped order: (0,0) (0,1)(1,1) (0,2)(1,2)(2,2) (0,3)(1,3)(2,3)(3,3)
__constant__ int c_gi[10] = {0,0,1,0,1,2,0,1,2,3};
__constant__ int c_gj[10] = {0,1,1,2,2,2,3,3,3,3};

// ---------------------------------------------------------------------------
// Kernel 1: batched Q = A^T A, upper-triangular 64x64 tiles only.
// ---------------------------------------------------------------------------
__global__ __launch_bounds__(256) void qbuild_kernel(const float* __restrict__ A) {
    __shared__ float As[32][64];
    __shared__ float Bs[32][64];
    const int blk = blockIdx.x;
    const int b   = blockIdx.z;
    const int i0  = c_gi[blk] * 64;
    const int j0  = c_gj[blk] * 64;
    const float* Ab = A + (size_t)b * NA * NA;
    float*       Qb = g_Qs + ((size_t)b * 10 + blk) * 4096;
    const int t  = threadIdx.x;
    const int ty = t >> 4;
    const int tx = t & 15;

    float acc[4][4];
#pragma unroll
    for (int r = 0; r < 4; r++)
#pragma unroll
        for (int s = 0; s < 4; s++) acc[r][s] = 0.0f;

    for (int k0 = 0; k0 < NA; k0 += 32) {
        __syncthreads();
#pragma unroll
        for (int r = 0; r < 8; r++) {
            int idx = t + 256 * r;
            int kk = idx >> 6, c = idx & 63;
            As[kk][c] = Ab[(size_t)(k0 + kk) * NA + i0 + c];
            Bs[kk][c] = Ab[(size_t)(k0 + kk) * NA + j0 + c];
        }
        __syncthreads();
#pragma unroll
        for (int kk = 0; kk < 32; kk++) {
            float4 a4 = *(const float4*)&As[kk][ty * 4];
            float4 b4 = *(const float4*)&Bs[kk][tx * 4];
            float av[4] = {a4.x, a4.y, a4.z, a4.w};
            float bv[4] = {b4.x, b4.y, b4.z, b4.w};
#pragma unroll
            for (int r = 0; r < 4; r++)
#pragma unroll
                for (int s = 0; s < 4; s++)
                    acc[r][s] = fmaf(av[r], bv[s], acc[r][s]);
        }
    }
#pragma unroll
    for (int r = 0; r < 4; r++) {
        float4 o = make_float4(acc[r][0], acc[r][1], acc[r][2], acc[r][3]);
        *(float4*)&Qb[(ty * 4 + r) * 64 + tx * 4] = o;
    }
}

// ---------------------------------------------------------------------------
// Packed f32x2 helpers (Blackwell FFMA2 — PTX-only)
// ---------------------------------------------------------------------------
__device__ __forceinline__ void ffma2u(ull& d, ull a, ull b) {
    asm("fma.rn.f32x2 %0, %1, %2, %0;" : "+l"(d) : "l"(a), "l"(b));
}
__device__ __forceinline__ void fadd2u(ull& d, ull a) {
    asm("add.rn.f32x2 %0, %0, %1;" : "+l"(d) : "l"(a));
}

__device__ __forceinline__ unsigned fkey(float x) {
    unsigned u = __float_as_uint(x);
    return u ^ (unsigned)(((int)u >> 31) | 0x80000000);
}
__device__ __forceinline__ float fkey_inv(unsigned k) {
    unsigned u = (k & 0x80000000u) ? (k ^ 0x80000000u) : ~k;
    return __uint_as_float(u);
}

__device__ __forceinline__ void warp_sum3(float& a, float& b, float& c) {
#pragma unroll
    for (int off = 16; off; off >>= 1) {
        a += __shfl_xor_sync(0xffffffffu, a, off);
        b += __shfl_xor_sync(0xffffffffu, b, off);
        c += __shfl_xor_sync(0xffffffffu, c, off);
    }
}
__device__ __forceinline__ void warp_sum2(float& a, float& b) {
#pragma unroll
    for (int off = 16; off; off >>= 1) {
        a += __shfl_xor_sync(0xffffffffu, a, off);
        b += __shfl_xor_sync(0xffffffffu, b, off);
    }
}
__device__ __forceinline__ float warp_sum(float v) {
#pragma unroll
    for (int off = 16; off; off >>= 1)
        v += __shfl_xor_sync(0xffffffffu, v, off);
    return v;
}
__device__ __forceinline__ float clipc(float z) {
    return fminf(fmaxf(z, -CMAX), CMAX);
}

// ---------------------------------------------------------------------------
// Kernel 2: per-batch solver. Q register-resident as f32x2 pairs.
// 512 threads; thread (ty=t>>4 in 0..31, tx=t&15) owns rows {ty,ty+32} x
// cols 4tx..4tx+3 of each of the 10 upper-tri blocks (80 floats = 40 ull).
// ---------------------------------------------------------------------------
__global__ __launch_bounds__(512) void solver_kernel(float* __restrict__ out) {
    extern __shared__ __align__(16) float red[];          // 16 * 256 floats
    __shared__ __align__(16) float  ys[NA];
    __shared__ __align__(16) float2 ys2[NA];              // (y,y) duplicated pairs
    __shared__ __align__(16) float  vs[NA];
    __shared__ __align__(16) float  rowsum[NA];
    __shared__ float scal[1];

    const int b  = blockIdx.x;
    const int t  = threadIdx.x;
    const int ty = t >> 4;
    const int tx = t & 15;

    // ---- load this thread's Q slice into registers as f32x2 pairs ----
    ull qq[20][2];
    {
        const float* Qb = g_Qs + (size_t)b * 10 * 4096;
#pragma unroll
        for (int qidx = 0; qidx < 10; qidx++)
#pragma unroll
            for (int k = 0; k < 2; k++) {
                ulonglong2 u = *(const ulonglong2*)&Qb[qidx * 4096 + (ty + 32 * k) * 64 + 4 * tx];
                qq[qidx * 2 + k][0] = u.x;
                qq[qidx * 2 + k][1] = u.y;
            }
    }
    if (t < NA) {
        ys[t] = 0.0625f;
        ys2[t] = make_float2(0.0625f, 0.0625f);
        rowsum[t] = 0.0f;
    }
    __syncthreads();

    // ---- symv: z[t] = (Q y)[t] for t<256, using symmetry ----
    auto symv = [&]() -> float {
        ull racc[3][2];
#pragma unroll
        for (int gi = 0; gi < 3; gi++)
#pragma unroll
            for (int k = 0; k < 2; k++) racc[gi][k] = 0ull;

        int qidx = 0;
#pragma unroll
        for (int gj = 0; gj < 4; gj++) {
            ull c01 = 0ull, c23 = 0ull;
            ull yj01 = *(const ull*)&ys[gj * 64 + 4 * tx];
            ull yj23 = *(const ull*)&ys[gj * 64 + 4 * tx + 2];
#pragma unroll
            for (int gi = 0; gi <= gj; gi++) {
                ull yi0 = *(const ull*)&ys2[gi * 64 + ty];
                ull yi1 = *(const ull*)&ys2[gi * 64 + ty + 32];
                ffma2u(c01, qq[qidx * 2 + 0][0], yi0);
                ffma2u(c23, qq[qidx * 2 + 0][1], yi0);
                ffma2u(c01, qq[qidx * 2 + 1][0], yi1);
                ffma2u(c23, qq[qidx * 2 + 1][1], yi1);
                if (gi != gj) {
                    ffma2u(racc[gi][0], qq[qidx * 2 + 0][0], yj01);
                    ffma2u(racc[gi][0], qq[qidx * 2 + 0][1], yj23);
                    ffma2u(racc[gi][1], qq[qidx * 2 + 1][0], yj01);
                    ffma2u(racc[gi][1], qq[qidx * 2 + 1][1], yj23);
                }
                qidx++;
            }
            // combine ty-parity pairs, store 16-row partials for segment gj
            ull o01 = __shfl_xor_sync(0xffffffffu, c01, 16);
            ull o23 = __shfl_xor_sync(0xffffffffu, c23, 16);
            fadd2u(c01, o01);
            fadd2u(c23, o23);
            if (!(ty & 1)) {
                *(ull*)&red[(ty >> 1) * NA + gj * 64 + 4 * tx]     = c01;
                *(ull*)&red[(ty >> 1) * NA + gj * 64 + 4 * tx + 2] = c23;
            }
        }

        // row-path: horizontal add then half-warp (16 tx lanes) reduce
#pragma unroll
        for (int gi = 0; gi < 3; gi++)
#pragma unroll
            for (int k = 0; k < 2; k++) {
                float2 rp = *(float2*)&racc[gi][k];
                float v = rp.x + rp.y;
                v += __shfl_xor_sync(0xffffffffu, v, 1);
                v += __shfl_xor_sync(0xffffffffu, v, 2);
                v += __shfl_xor_sync(0xffffffffu, v, 4);
                v += __shfl_xor_sync(0xffffffffu, v, 8);
                if (tx == 0) rowsum[gi * 64 + ty + 32 * k] += v;
            }
        __syncthreads();

        float z = 0.0f;
        if (t < NA) {
            z = rowsum[t];
#pragma unroll
            for (int q = 0; q < 16; q++) z += red[q * NA + t];
            rowsum[t] = 0.0f;   // reset own slot; caller barriers before next symv
        }
        return z;
    };

    // ---------------- power iteration for lambda_max ----------------
    for (int it = 0; it < PITERS; it++) {
        float z = symv();
        if (t < NA) vs[t] = z;
        __syncthreads();
        if (t < 32) {
            float zr[8];
            float ss = 0.0f;
#pragma unroll
            for (int k = 0; k < 8; k++) { zr[k] = vs[t + 32 * k]; ss = fmaf(zr[k], zr[k], ss); }
            ss = warp_sum(ss);
            float inv = 1.0f / (sqrtf(ss) + 1e-12f);
#pragma unroll
            for (int k = 0; k < 8; k++) {
                float yv = zr[k] * inv;
                ys[t + 32 * k] = yv;
                ys2[t + 32 * k] = make_float2(yv, yv);
            }
        }
        __syncthreads();
    }
    {
        float z = symv();
        if (t < NA) vs[t] = z;
        __syncthreads();
        if (t < 32) {
            float ss = 0.0f;
#pragma unroll
            for (int k = 0; k < 8; k++) ss = fmaf(ys[t + 32 * k], vs[t + 32 * k], ss);
            ss = warp_sum(ss);
            if (t == 0) scal[0] = 1.0f / (2.0f * ss + 1e-12f);
        }
        __syncthreads();
    }
    const float step = scal[0];

    // ---------------- FISTA ----------------
    float wreg = 1.0f / 256.0f;
    float tf = 1.0f;
    if (t < NA) {
        ys[t] = wreg;
        ys2[t] = make_float2(wreg, wreg);
    }
    __syncthreads();

    for (int it = 0; it < NITERS; it++) {
        float z = symv();
        if (t < NA) vs[t] = ys[t] - step * (2.0f * z);
        __syncthreads();

        if (t < NA) {
            const int lane = t & 31;
            float vr[8];
#pragma unroll
            for (int k = 0; k < 8; k++) vr[k] = vs[lane + 32 * k];

            // bracket via orderable-bits redux min/max (exact)
            float mn = vr[0], mx = vr[0];
#pragma unroll
            for (int k = 1; k < 8; k++) { mn = fminf(mn, vr[k]); mx = fmaxf(mx, vr[k]); }
            unsigned kmn = __reduce_min_sync(0xffffffffu, fkey(mn));
            unsigned kmx = __reduce_max_sync(0xffffffffu, fkey(mx));
            float lo = fkey_inv(kmn) - CMAX;
            float hi = fkey_inv(kmx) + CMAX;

            // 3 quartile rounds (64x bracket shrink) — round-9 proven recipe
            for (int r = 0; r < QUADROUNDS; r++) {
                float d  = hi - lo;
                float m1 = lo + 0.25f * d;
                float m2 = lo + 0.50f * d;
                float m3 = lo + 0.75f * d;
                float s1 = 0.0f, s2 = 0.0f, s3 = 0.0f;
#pragma unroll
                for (int k = 0; k < 8; k++) {
                    s1 += clipc(vr[k] - m1);
                    s2 += clipc(vr[k] - m2);
                    s3 += clipc(vr[k] - m3);
                }
                warp_sum3(s1, s2, s3);
                if (s2 > 1.0f) {
                    bool p3 = s3 > 1.0f;
                    lo = p3 ? m3 : m2;
                    hi = p3 ? hi : m3;
                } else {
                    bool p1 = s1 > 1.0f;
                    lo = p1 ? m1 : lo;
                    hi = p1 ? m2 : m1;
                }
            }
            float tau0 = 0.5f * (lo + hi);
            // safeguarded Newton (float shfl sums — exact round-9 math)
            for (int r = 0; r < NEWTONROUNDS; r++) {
                float s = 0.0f, cnt = 0.0f;
#pragma unroll
                for (int k = 0; k < 8; k++) {
                    float zz = vr[k] - tau0;
                    s += clipc(zz);
                    cnt += (fabsf(zz) < CMAX) ? 1.0f : 0.0f;
                }
                warp_sum2(s, cnt);
                bool p = s > 1.0f;
                lo = p ? tau0 : lo;
                hi = p ? hi : tau0;
                float nt = tau0 + (s - 1.0f) / fmaxf(cnt, 1.0f);
                tau0 = (nt > lo && nt < hi) ? nt : 0.5f * (lo + hi);
            }

            // exact tau from active set (matches reference recompute)
            float sv = 0.0f, cntf = 0.0f, dk = 0.0f;
#pragma unroll
            for (int k = 0; k < 8; k++) {
                float zz = vr[k] - tau0;
                bool in = fabsf(zz) < CMAX;
                if (in) { sv += vr[k]; cntf += 1.0f; }
                else    { dk += (zz >= CMAX) ? 1.0f : -1.0f; }
            }
            warp_sum3(sv, cntf, dk);
            float tau = (sv + CMAX * dk - 1.0f) / fmaxf(cntf, 1.0f);

            // fused momentum update (vs[t] == vr[t>>5])
            float tn = 0.5f * (1.0f + sqrtf(1.0f + 4.0f * tf * tf));
            float wn = clipc(vr[t >> 5] - tau);
            float yn = wn + ((tf - 1.0f) / tn) * (wn - wreg);
            wreg = wn;
            tf = tn;
            ys[t] = yn;
            ys2[t] = make_float2(yn, yn);
        }
        __syncthreads();
    }

    if (t < NA) out[(size_t)b * NA + t] = wreg;
}

// ---------------------------------------------------------------------------
extern "C" void kernel_launch(void* const* d_in, const int* in_sizes, int n_in,
                              void* d_out, int out_size) {
    (void)in_sizes; (void)n_in; (void)out_size;
    const float* A = (const float*)d_in[0];
    float* out = (float*)d_out;

    const int dyn_smem = 16 * NA * sizeof(float);   // 16 KB
    cudaFuncSetAttribute(solver_kernel,
                         cudaFuncAttributeMaxDynamicSharedMemorySize, dyn_smem);

    qbuild_kernel<<<dim3(10, 1, NB), 256>>>(A);
    solver_kernel<<<NB, 512, dyn_smem>>>(out);
}

// round 13
// speedup vs baseline: 1.1112x; 1.1112x over previous
#include <cuda_runtime.h>

#define NA 256
#define NB 512
#define CMAX 0.05f
#define NITERS 300
#define PITERS 30
#define QUADROUNDS 3
#define NEWTONROUNDS 6

typedef unsigned long long ull;

// Upper-triangular Q blocks, fp32: 512 batches * 10 blocks * 64*64 floats = 82 MB
__device__ float g_Qs[(size_t)NB * 10 * 4096];

// gj-grouped order: (0,0) (0,1)(1,1) (0,2)(1,2)(2,2) (0,3)(1,3)(2,3)(3,3)
__constant__ int c_gi[10] = {0,0,1,0,1,2,0,1,2,3};
__constant__ int c_gj[10] = {0,1,1,2,2,2,3,3,3,3};

// ---------------------------------------------------------------------------
// Kernel 1: batched Q = A^T A, upper-triangular 64x64 tiles only.
// ---------------------------------------------------------------------------
__global__ __launch_bounds__(256) void qbuild_kernel(const float* __restrict__ A) {
    __shared__ float As[32][64];
    __shared__ float Bs[32][64];
    const int blk = blockIdx.x;
    const int b   = blockIdx.z;
    const int i0  = c_gi[blk] * 64;
    const int j0  = c_gj[blk] * 64;
    const float* Ab = A + (size_t)b * NA * NA;
    float*       Qb = g_Qs + ((size_t)b * 10 + blk) * 4096;
    const int t  = threadIdx.x;
    const int ty = t >> 4;
    const int tx = t & 15;

    float acc[4][4];
#pragma unroll
    for (int r = 0; r < 4; r++)
#pragma unroll
        for (int s = 0; s < 4; s++) acc[r][s] = 0.0f;

    for (int k0 = 0; k0 < NA; k0 += 32) {
        __syncthreads();
#pragma unroll
        for (int r = 0; r < 8; r++) {
            int idx = t + 256 * r;
            int kk = idx >> 6, c = idx & 63;
            As[kk][c] = Ab[(size_t)(k0 + kk) * NA + i0 + c];
            Bs[kk][c] = Ab[(size_t)(k0 + kk) * NA + j0 + c];
        }
        __syncthreads();
#pragma unroll
        for (int kk = 0; kk < 32; kk++) {
            float4 a4 = *(const float4*)&As[kk][ty * 4];
            float4 b4 = *(const float4*)&Bs[kk][tx * 4];
            float av[4] = {a4.x, a4.y, a4.z, a4.w};
            float bv[4] = {b4.x, b4.y, b4.z, b4.w};
#pragma unroll
            for (int r = 0; r < 4; r++)
#pragma unroll
                for (int s = 0; s < 4; s++)
                    acc[r][s] = fmaf(av[r], bv[s], acc[r][s]);
        }
    }
#pragma unroll
    for (int r = 0; r < 4; r++) {
        float4 o = make_float4(acc[r][0], acc[r][1], acc[r][2], acc[r][3]);
        *(float4*)&Qb[(ty * 4 + r) * 64 + tx * 4] = o;
    }
}

// ---------------------------------------------------------------------------
// Packed f32x2 helpers (Blackwell FFMA2 — PTX-only)
// ---------------------------------------------------------------------------
__device__ __forceinline__ void ffma2u(ull& d, ull a, ull b) {
    asm("fma.rn.f32x2 %0, %1, %2, %0;" : "+l"(d) : "l"(a), "l"(b));
}
__device__ __forceinline__ void fadd2u(ull& d, ull a) {
    asm("add.rn.f32x2 %0, %0, %1;" : "+l"(d) : "l"(a));
}

__device__ __forceinline__ unsigned fkey(float x) {
    unsigned u = __float_as_uint(x);
    return u ^ (unsigned)(((int)u >> 31) | 0x80000000);
}
__device__ __forceinline__ float fkey_inv(unsigned k) {
    unsigned u = (k & 0x80000000u) ? (k ^ 0x80000000u) : ~k;
    return __uint_as_float(u);
}

__device__ __forceinline__ void warp_sum3(float& a, float& b, float& c) {
#pragma unroll
    for (int off = 16; off; off >>= 1) {
        a += __shfl_xor_sync(0xffffffffu, a, off);
        b += __shfl_xor_sync(0xffffffffu, b, off);
        c += __shfl_xor_sync(0xffffffffu, c, off);
    }
}
__device__ __forceinline__ void warp_sum2(float& a, float& b) {
#pragma unroll
    for (int off = 16; off; off >>= 1) {
        a += __shfl_xor_sync(0xffffffffu, a, off);
        b += __shfl_xor_sync(0xffffffffu, b, off);
    }
}
__device__ __forceinline__ float warp_sum(float v) {
#pragma unroll
    for (int off = 16; off; off >>= 1)
        v += __shfl_xor_sync(0xffffffffu, v, off);
    return v;
}
__device__ __forceinline__ float clipc(float z) {
    return fminf(fmaxf(z, -CMAX), CMAX);
}

// ---------------------------------------------------------------------------
// Kernel 2: per-batch solver. Q register-resident as f32x2 pairs.
// 512 threads; thread (ty=t>>4 in 0..31, tx=t&15) owns rows {ty,ty+32} x
// cols 4tx..4tx+3 of each of the 10 upper-tri blocks (80 floats = 40 ull).
// Projection: warp 0 only (serial latency, no issue multiplication).
// ---------------------------------------------------------------------------
__global__ __launch_bounds__(512) void solver_kernel(float* __restrict__ out) {
    extern __shared__ __align__(16) float red[];          // 16 * 256 floats
    __shared__ __align__(16) float  ys[NA];
    __shared__ __align__(16) float2 ys2[NA];              // (y,y) duplicated pairs
    __shared__ __align__(16) float  vs[NA];
    __shared__ __align__(16) float  rowsum[NA];
    __shared__ float scal[2];

    const int b  = blockIdx.x;
    const int t  = threadIdx.x;
    const int ty = t >> 4;
    const int tx = t & 15;

    // ---- load this thread's Q slice into registers as f32x2 pairs ----
    ull qq[20][2];
    {
        const float* Qb = g_Qs + (size_t)b * 10 * 4096;
#pragma unroll
        for (int qidx = 0; qidx < 10; qidx++)
#pragma unroll
            for (int k = 0; k < 2; k++) {
                ulonglong2 u = *(const ulonglong2*)&Qb[qidx * 4096 + (ty + 32 * k) * 64 + 4 * tx];
                qq[qidx * 2 + k][0] = u.x;
                qq[qidx * 2 + k][1] = u.y;
            }
    }
    if (t < NA) {
        ys[t] = 0.0625f;
        ys2[t] = make_float2(0.0625f, 0.0625f);
        rowsum[t] = 0.0f;
    }
    __syncthreads();

    // ---- symv: z[t] = (Q y)[t] for t<256, using symmetry ----
    auto symv = [&]() -> float {
        ull racc[3][2];
#pragma unroll
        for (int gi = 0; gi < 3; gi++)
#pragma unroll
            for (int k = 0; k < 2; k++) racc[gi][k] = 0ull;

        int qidx = 0;
#pragma unroll
        for (int gj = 0; gj < 4; gj++) {
            ull c01 = 0ull, c23 = 0ull;
            ull yj01 = *(const ull*)&ys[gj * 64 + 4 * tx];
            ull yj23 = *(const ull*)&ys[gj * 64 + 4 * tx + 2];
#pragma unroll
            for (int gi = 0; gi <= gj; gi++) {
                ull yi0 = *(const ull*)&ys2[gi * 64 + ty];
                ull yi1 = *(const ull*)&ys2[gi * 64 + ty + 32];
                ffma2u(c01, qq[qidx * 2 + 0][0], yi0);
                ffma2u(c23, qq[qidx * 2 + 0][1], yi0);
                ffma2u(c01, qq[qidx * 2 + 1][0], yi1);
                ffma2u(c23, qq[qidx * 2 + 1][1], yi1);
                if (gi != gj) {
                    ffma2u(racc[gi][0], qq[qidx * 2 + 0][0], yj01);
                    ffma2u(racc[gi][0], qq[qidx * 2 + 0][1], yj23);
                    ffma2u(racc[gi][1], qq[qidx * 2 + 1][0], yj01);
                    ffma2u(racc[gi][1], qq[qidx * 2 + 1][1], yj23);
                }
                qidx++;
            }
            // combine ty-parity pairs, store 16-row partials for segment gj
            ull o01 = __shfl_xor_sync(0xffffffffu, c01, 16);
            ull o23 = __shfl_xor_sync(0xffffffffu, c23, 16);
            fadd2u(c01, o01);
            fadd2u(c23, o23);
            if (!(ty & 1)) {
                *(ull*)&red[(ty >> 1) * NA + gj * 64 + 4 * tx]     = c01;
                *(ull*)&red[(ty >> 1) * NA + gj * 64 + 4 * tx + 2] = c23;
            }
        }

        // row-path: horizontal add then half-warp (16 tx lanes) reduce
#pragma unroll
        for (int gi = 0; gi < 3; gi++)
#pragma unroll
            for (int k = 0; k < 2; k++) {
                float2 rp = *(float2*)&racc[gi][k];
                float v = rp.x + rp.y;
                v += __shfl_xor_sync(0xffffffffu, v, 1);
                v += __shfl_xor_sync(0xffffffffu, v, 2);
                v += __shfl_xor_sync(0xffffffffu, v, 4);
                v += __shfl_xor_sync(0xffffffffu, v, 8);
                if (tx == 0) rowsum[gi * 64 + ty + 32 * k] += v;
            }
        __syncthreads();

        float z = 0.0f;
        if (t < NA) {
            z = rowsum[t];
#pragma unroll
            for (int q = 0; q < 16; q++) z += red[q * NA + t];
            rowsum[t] = 0.0f;   // reset own slot; caller barriers before next symv
        }
        return z;
    };

    // ---------------- power iteration for lambda_max ----------------
    for (int it = 0; it < PITERS; it++) {
        float z = symv();
        if (t < NA) vs[t] = z;
        __syncthreads();
        if (t < 32) {
            float zr[8];
            float ss = 0.0f;
#pragma unroll
            for (int k = 0; k < 8; k++) { zr[k] = vs[t + 32 * k]; ss = fmaf(zr[k], zr[k], ss); }
            ss = warp_sum(ss);
            float inv = 1.0f / (sqrtf(ss) + 1e-12f);
#pragma unroll
            for (int k = 0; k < 8; k++) {
                float yv = zr[k] * inv;
                ys[t + 32 * k] = yv;
                ys2[t + 32 * k] = make_float2(yv, yv);
            }
        }
        __syncthreads();
    }
    {
        float z = symv();
        if (t < NA) vs[t] = z;
        __syncthreads();
        if (t < 32) {
            float ss = 0.0f;
#pragma unroll
            for (int k = 0; k < 8; k++) ss = fmaf(ys[t + 32 * k], vs[t + 32 * k], ss);
            ss = warp_sum(ss);
            if (t == 0) scal[0] = 1.0f / (2.0f * ss + 1e-12f);
        }
        __syncthreads();
    }
    const float step = scal[0];

    // ---------------- FISTA ----------------
    float wreg = 1.0f / 256.0f;
    float tf = 1.0f;
    if (t < NA) {
        ys[t] = wreg;
        ys2[t] = make_float2(wreg, wreg);
    }
    __syncthreads();

    for (int it = 0; it < NITERS; it++) {
        float z = symv();
        if (t < NA) vs[t] = ys[t] - step * (2.0f * z);
        __syncthreads();

        // --- projection on WARP 0 ONLY: redux bracket + quartile + Newton ---
        if (t < 32) {
            float vr[8];
#pragma unroll
            for (int k = 0; k < 8; k++) vr[k] = vs[t + 32 * k];

            // bracket via orderable-bits redux min/max (exact)
            float mn = vr[0], mx = vr[0];
#pragma unroll
            for (int k = 1; k < 8; k++) { mn = fminf(mn, vr[k]); mx = fmaxf(mx, vr[k]); }
            unsigned kmn = __reduce_min_sync(0xffffffffu, fkey(mn));
            unsigned kmx = __reduce_max_sync(0xffffffffu, fkey(mx));
            float lo = fkey_inv(kmn) - CMAX;
            float hi = fkey_inv(kmx) + CMAX;

            // 3 quartile rounds (64x bracket shrink)
            for (int r = 0; r < QUADROUNDS; r++) {
                float d  = hi - lo;
                float m1 = lo + 0.25f * d;
                float m2 = lo + 0.50f * d;
                float m3 = lo + 0.75f * d;
                float s1 = 0.0f, s2 = 0.0f, s3 = 0.0f;
#pragma unroll
                for (int k = 0; k < 8; k++) {
                    s1 += clipc(vr[k] - m1);
                    s2 += clipc(vr[k] - m2);
                    s3 += clipc(vr[k] - m3);
                }
                warp_sum3(s1, s2, s3);
                if (s2 > 1.0f) {
                    bool p3 = s3 > 1.0f;
                    lo = p3 ? m3 : m2;
                    hi = p3 ? hi : m3;
                } else {
                    bool p1 = s1 > 1.0f;
                    lo = p1 ? m1 : lo;
                    hi = p1 ? m2 : m1;
                }
            }
            float tau0 = 0.5f * (lo + hi);
            // safeguarded Newton
            for (int r = 0; r < NEWTONROUNDS; r++) {
                float s = 0.0f, cnt = 0.0f;
#pragma unroll
                for (int k = 0; k < 8; k++) {
                    float zz = vr[k] - tau0;
                    s += clipc(zz);
                    cnt += (fabsf(zz) < CMAX) ? 1.0f : 0.0f;
                }
                warp_sum2(s, cnt);
                bool p = s > 1.0f;
                lo = p ? tau0 : lo;
                hi = p ? hi : tau0;
                float nt = tau0 + (s - 1.0f) / fmaxf(cnt, 1.0f);
                tau0 = (nt > lo && nt < hi) ? nt : 0.5f * (lo + hi);
            }

            // exact tau from active set (matches reference recompute)
            float sv = 0.0f, cntf = 0.0f, dk = 0.0f;
#pragma unroll
            for (int k = 0; k < 8; k++) {
                float zz = vr[k] - tau0;
                bool in = fabsf(zz) < CMAX;
                if (in) { sv += vr[k]; cntf += 1.0f; }
                else    { dk += (zz >= CMAX) ? 1.0f : -1.0f; }
            }
            warp_sum3(sv, cntf, dk);
            float tau = (sv + CMAX * dk - 1.0f) / fmaxf(cntf, 1.0f);
            if (t == 0) scal[1] = tau;
        }
        __syncthreads();

        // --- momentum update (all t<256; wreg is this thread's w) ---
        {
            float tn = 0.5f * (1.0f + sqrtf(1.0f + 4.0f * tf * tf));
            if (t < NA) {
                float tau = scal[1];
                float wn = clipc(vs[t] - tau);
                float yn = wn + ((tf - 1.0f) / tn) * (wn - wreg);
                wreg = wn;
                ys[t] = yn;
                ys2[t] = make_float2(yn, yn);
            }
            tf = tn;
        }
        __syncthreads();
    }

    if (t < NA) out[(size_t)b * NA + t] = wreg;
}

// ---------------------------------------------------------------------------
extern "C" void kernel_launch(void* const* d_in, const int* in_sizes, int n_in,
                              void* d_out, int out_size) {
    (void)in_sizes; (void)n_in; (void)out_size;
    const float* A = (const float*)d_in[0];
    float* out = (float*)d_out;

    const int dyn_smem = 16 * NA * sizeof(float);   // 16 KB
    cudaFuncSetAttribute(solver_kernel,
                         cudaFuncAttributeMaxDynamicSharedMemorySize, dyn_smem);

    qbuild_kernel<<<dim3(10, 1, NB), 256>>>(A);
    solver_kernel<<<NB, 512, dyn_smem>>>(out);
}

// round 14
// speedup vs baseline: 1.4425x; 1.2982x over previous
#include <cuda_runtime.h>

#define NA 256
#define NB 512
#define CMAX 0.05f
#define NITERS 300
#define PITERS 30
#define QUADROUNDS 3
#define NEWTONROUNDS 6

typedef unsigned long long ull;

// Upper-triangular Q blocks, fp32: 512 batches * 10 blocks * 64*64 floats = 82 MB
__device__ float g_Qs[(size_t)NB * 10 * 4096];

// gj-grouped order: (0,0) (0,1)(1,1) (0,2)(1,2)(2,2) (0,3)(1,3)(2,3)(3,3)
__constant__ int c_gi[10] = {0,0,1,0,1,2,0,1,2,3};
__constant__ int c_gj[10] = {0,1,1,2,2,2,3,3,3,3};

// ---------------------------------------------------------------------------
// Kernel 1: batched Q = A^T A, upper-triangular 64x64 tiles only.
// ---------------------------------------------------------------------------
__global__ __launch_bounds__(256) void qbuild_kernel(const float* __restrict__ A) {
    __shared__ float As[32][64];
    __shared__ float Bs[32][64];
    const int blk = blockIdx.x;
    const int b   = blockIdx.z;
    const int i0  = c_gi[blk] * 64;
    const int j0  = c_gj[blk] * 64;
    const float* Ab = A + (size_t)b * NA * NA;
    float*       Qb = g_Qs + ((size_t)b * 10 + blk) * 4096;
    const int t  = threadIdx.x;
    const int ty = t >> 4;
    const int tx = t & 15;

    float acc[4][4];
#pragma unroll
    for (int r = 0; r < 4; r++)
#pragma unroll
        for (int s = 0; s < 4; s++) acc[r][s] = 0.0f;

    for (int k0 = 0; k0 < NA; k0 += 32) {
        __syncthreads();
#pragma unroll
        for (int r = 0; r < 8; r++) {
            int idx = t + 256 * r;
            int kk = idx >> 6, c = idx & 63;
            As[kk][c] = Ab[(size_t)(k0 + kk) * NA + i0 + c];
            Bs[kk][c] = Ab[(size_t)(k0 + kk) * NA + j0 + c];
        }
        __syncthreads();
#pragma unroll
        for (int kk = 0; kk < 32; kk++) {
            float4 a4 = *(const float4*)&As[kk][ty * 4];
            float4 b4 = *(const float4*)&Bs[kk][tx * 4];
            float av[4] = {a4.x, a4.y, a4.z, a4.w};
            float bv[4] = {b4.x, b4.y, b4.z, b4.w};
#pragma unroll
            for (int r = 0; r < 4; r++)
#pragma unroll
                for (int s = 0; s < 4; s++)
                    acc[r][s] = fmaf(av[r], bv[s], acc[r][s]);
        }
    }
#pragma unroll
    for (int r = 0; r < 4; r++) {
        float4 o = make_float4(acc[r][0], acc[r][1], acc[r][2], acc[r][3]);
        *(float4*)&Qb[(ty * 4 + r) * 64 + tx * 4] = o;
    }
}

// ---------------------------------------------------------------------------
// Packed f32x2 helpers
// ---------------------------------------------------------------------------
__device__ __forceinline__ void ffma2u(ull& d, ull a, ull b) {
    asm("fma.rn.f32x2 %0, %1, %2, %0;" : "+l"(d) : "l"(a), "l"(b));
}
__device__ __forceinline__ void fadd2u(ull& d, ull a) {
    asm("add.rn.f32x2 %0, %0, %1;" : "+l"(d) : "l"(a));
}

__device__ __forceinline__ unsigned fkey(float x) {
    unsigned u = __float_as_uint(x);
    return u ^ (unsigned)(((int)u >> 31) | 0x80000000);
}
__device__ __forceinline__ float fkey_inv(unsigned k) {
    unsigned u = (k & 0x80000000u) ? (k ^ 0x80000000u) : ~k;
    return __uint_as_float(u);
}

__device__ __forceinline__ void warp_sum3(float& a, float& b, float& c) {
#pragma unroll
    for (int off = 16; off; off >>= 1) {
        a += __shfl_xor_sync(0xffffffffu, a, off);
        b += __shfl_xor_sync(0xffffffffu, b, off);
        c += __shfl_xor_sync(0xffffffffu, c, off);
    }
}
__device__ __forceinline__ void warp_sum2(float& a, float& b) {
#pragma unroll
    for (int off = 16; off; off >>= 1) {
        a += __shfl_xor_sync(0xffffffffu, a, off);
        b += __shfl_xor_sync(0xffffffffu, b, off);
    }
}
__device__ __forceinline__ float warp_sum(float v) {
#pragma unroll
    for (int off = 16; off; off >>= 1)
        v += __shfl_xor_sync(0xffffffffu, v, off);
    return v;
}
__device__ __forceinline__ float clipc(float z) {
    return fminf(fmaxf(z, -CMAX), CMAX);
}

// ---------------------------------------------------------------------------
// Kernel 2: per-batch solver, 256 threads, 2 CTAs/SM.
// Thread (ty=t>>3 in 0..31, tx=t&7) owns rows {ty, ty+32} x cols 8tx..8tx+7
// of each block. Blocks 0..4 register-resident (80 regs), blocks 5..9 in smem.
// ---------------------------------------------------------------------------
__global__ __launch_bounds__(256, 2) void solver_kernel(float* __restrict__ out) {
    extern __shared__ __align__(16) float sdyn[];   // Qsm[5*4096] + red[8*256]
    float* Qsm = sdyn;
    float* red = sdyn + 5 * 4096;
    __shared__ __align__(16) float  ys[NA];
    __shared__ __align__(16) float2 ys2[NA];        // (y,y) duplicated pairs
    __shared__ __align__(16) float  vs[NA];
    __shared__ __align__(16) float  rowsum[NA];
    __shared__ float scal[2];

    const int b  = blockIdx.x;
    const int t  = threadIdx.x;
    const int ty = t >> 3;          // 0..31
    const int tx = t & 7;           // 0..7
    const int w  = t >> 5;          // warp 0..7
    const float* Qb = g_Qs + (size_t)b * 10 * 4096;

    // ---- register half: blocks 0..4, rows {ty, ty+32}, cols 8tx..8tx+7 ----
    ull qq[5][2][4];
#pragma unroll
    for (int q = 0; q < 5; q++)
#pragma unroll
        for (int k = 0; k < 2; k++) {
            const float* src = Qb + q * 4096 + (ty + 32 * k) * 64 + 8 * tx;
            ulonglong2 u0 = *(const ulonglong2*)(src);
            ulonglong2 u1 = *(const ulonglong2*)(src + 4);
            qq[q][k][0] = u0.x; qq[q][k][1] = u0.y;
            qq[q][k][2] = u1.x; qq[q][k][3] = u1.y;
        }
    // ---- smem half: blocks 5..9 copied verbatim ----
    {
        const float4* src = (const float4*)(Qb + 5 * 4096);
        float4* dst = (float4*)Qsm;
        for (int i = t; i < 5 * 1024; i += 256) dst[i] = src[i];
    }
    ys[t] = 0.0625f;
    ys2[t] = make_float2(0.0625f, 0.0625f);
    rowsum[t] = 0.0f;
    __syncthreads();

    // ---- symv: z[t] = (Q y)[t], symmetry-exploiting ----
    auto symv = [&]() -> float {
        ull racc[3][2];
#pragma unroll
        for (int gi = 0; gi < 3; gi++)
#pragma unroll
            for (int k = 0; k < 2; k++) racc[gi][k] = 0ull;

        int qidx = 0;
#pragma unroll
        for (int gj = 0; gj < 4; gj++) {
            ull cacc[4] = {0ull, 0ull, 0ull, 0ull};
            ull yj[4];
            {
                ulonglong2 u0 = *(const ulonglong2*)&ys[gj * 64 + 8 * tx];
                ulonglong2 u1 = *(const ulonglong2*)&ys[gj * 64 + 8 * tx + 4];
                yj[0] = u0.x; yj[1] = u0.y; yj[2] = u1.x; yj[3] = u1.y;
            }
#pragma unroll
            for (int gi = 0; gi <= gj; gi++) {
                ull q0[4], q1[4];
                if (qidx < 5) {
#pragma unroll
                    for (int c = 0; c < 4; c++) { q0[c] = qq[qidx][0][c]; q1[c] = qq[qidx][1][c]; }
                } else {
                    const float* srow = Qsm + (qidx - 5) * 4096 + ty * 64 + 8 * tx;
                    ulonglong2 a0 = *(const ulonglong2*)(srow);
                    ulonglong2 a1 = *(const ulonglong2*)(srow + 4);
                    ulonglong2 b0 = *(const ulonglong2*)(srow + 32 * 64);
                    ulonglong2 b1 = *(const ulonglong2*)(srow + 32 * 64 + 4);
                    q0[0] = a0.x; q0[1] = a0.y; q0[2] = a1.x; q0[3] = a1.y;
                    q1[0] = b0.x; q1[1] = b0.y; q1[2] = b1.x; q1[3] = b1.y;
                }
                ull yi0 = *(const ull*)&ys2[gi * 64 + ty];
                ull yi1 = *(const ull*)&ys2[gi * 64 + ty + 32];
#pragma unroll
                for (int c = 0; c < 4; c++) {
                    ffma2u(cacc[c], q0[c], yi0);
                    ffma2u(cacc[c], q1[c], yi1);
                }
                if (gi != gj) {
#pragma unroll
                    for (int c = 0; c < 4; c++) {
                        ffma2u(racc[gi][0], q0[c], yj[c]);
                        ffma2u(racc[gi][1], q1[c], yj[c]);
                    }
                }
                qidx++;
            }
            // reduce cacc over the 4 ty-subgroups within the warp
#pragma unroll
            for (int c = 0; c < 4; c++) {
                ull o8  = __shfl_xor_sync(0xffffffffu, cacc[c], 8);
                fadd2u(cacc[c], o8);
                ull o16 = __shfl_xor_sync(0xffffffffu, cacc[c], 16);
                fadd2u(cacc[c], o16);
            }
            if ((ty & 3) == 0) {
                *(ulonglong2*)&red[w * NA + gj * 64 + 8 * tx]     = make_ulonglong2(cacc[0], cacc[1]);
                *(ulonglong2*)&red[w * NA + gj * 64 + 8 * tx + 4] = make_ulonglong2(cacc[2], cacc[3]);
            }
        }

        // row path: horizontal add then reduce over the 8 tx lanes
#pragma unroll
        for (int gi = 0; gi < 3; gi++)
#pragma unroll
            for (int k = 0; k < 2; k++) {
                float2 rp = *(float2*)&racc[gi][k];
                float v = rp.x + rp.y;
                v += __shfl_xor_sync(0xffffffffu, v, 1);
                v += __shfl_xor_sync(0xffffffffu, v, 2);
                v += __shfl_xor_sync(0xffffffffu, v, 4);
                if (tx == 0) rowsum[gi * 64 + ty + 32 * k] += v;
            }
        __syncthreads();

        float z = rowsum[t];
#pragma unroll
        for (int q = 0; q < 8; q++) z += red[q * NA + t];
        rowsum[t] = 0.0f;   // reset own slot; caller barriers before next symv
        return z;
    };

    // ---------------- power iteration for lambda_max ----------------
    for (int it = 0; it < PITERS; it++) {
        float z = symv();
        vs[t] = z;
        __syncthreads();
        if (t < 32) {
            float zr[8];
            float ss = 0.0f;
#pragma unroll
            for (int k = 0; k < 8; k++) { zr[k] = vs[t + 32 * k]; ss = fmaf(zr[k], zr[k], ss); }
            ss = warp_sum(ss);
            float inv = 1.0f / (sqrtf(ss) + 1e-12f);
#pragma unroll
            for (int k = 0; k < 8; k++) {
                float yv = zr[k] * inv;
                ys[t + 32 * k] = yv;
                ys2[t + 32 * k] = make_float2(yv, yv);
            }
        }
        __syncthreads();
    }
    {
        float z = symv();
        vs[t] = z;
        __syncthreads();
        if (t < 32) {
            float ss = 0.0f;
#pragma unroll
            for (int k = 0; k < 8; k++) ss = fmaf(ys[t + 32 * k], vs[t + 32 * k], ss);
            ss = warp_sum(ss);
            if (t == 0) scal[0] = 1.0f / (2.0f * ss + 1e-12f);
        }
        __syncthreads();
    }
    const float step = scal[0];

    // ---------------- FISTA ----------------
    float wreg = 1.0f / 256.0f;
    float tf = 1.0f;
    ys[t] = wreg;
    ys2[t] = make_float2(wreg, wreg);
    __syncthreads();

    for (int it = 0; it < NITERS; it++) {
        float z = symv();
        vs[t] = ys[t] - step * (2.0f * z);
        __syncthreads();

        // --- projection on WARP 0 ONLY (round-13 proven recipe) ---
        if (t < 32) {
            float vr[8];
#pragma unroll
            for (int k = 0; k < 8; k++) vr[k] = vs[t + 32 * k];

            float mn = vr[0], mx = vr[0];
#pragma unroll
            for (int k = 1; k < 8; k++) { mn = fminf(mn, vr[k]); mx = fmaxf(mx, vr[k]); }
            unsigned kmn = __reduce_min_sync(0xffffffffu, fkey(mn));
            unsigned kmx = __reduce_max_sync(0xffffffffu, fkey(mx));
            float lo = fkey_inv(kmn) - CMAX;
            float hi = fkey_inv(kmx) + CMAX;

            for (int r = 0; r < QUADROUNDS; r++) {
                float d  = hi - lo;
                float m1 = lo + 0.25f * d;
                float m2 = lo + 0.50f * d;
                float m3 = lo + 0.75f * d;
                float s1 = 0.0f, s2 = 0.0f, s3 = 0.0f;
#pragma unroll
                for (int k = 0; k < 8; k++) {
                    s1 += clipc(vr[k] - m1);
                    s2 += clipc(vr[k] - m2);
                    s3 += clipc(vr[k] - m3);
                }
                warp_sum3(s1, s2, s3);
                if (s2 > 1.0f) {
                    bool p3 = s3 > 1.0f;
                    lo = p3 ? m3 : m2;
                    hi = p3 ? hi : m3;
                } else {
                    bool p1 = s1 > 1.0f;
                    lo = p1 ? m1 : lo;
                    hi = p1 ? m2 : m1;
                }
            }
            float tau0 = 0.5f * (lo + hi);
            for (int r = 0; r < NEWTONROUNDS; r++) {
                float s = 0.0f, cnt = 0.0f;
#pragma unroll
                for (int k = 0; k < 8; k++) {
                    float zz = vr[k] - tau0;
                    s += clipc(zz);
                    cnt += (fabsf(zz) < CMAX) ? 1.0f : 0.0f;
                }
                warp_sum2(s, cnt);
                bool p = s > 1.0f;
                lo = p ? tau0 : lo;
                hi = p ? hi : tau0;
                float nt = tau0 + (s - 1.0f) / fmaxf(cnt, 1.0f);
                tau0 = (nt > lo && nt < hi) ? nt : 0.5f * (lo + hi);
            }

            float sv = 0.0f, cntf = 0.0f, dk = 0.0f;
#pragma unroll
            for (int k = 0; k < 8; k++) {
                float zz = vr[k] - tau0;
                bool in = fabsf(zz) < CMAX;
                if (in) { sv += vr[k]; cntf += 1.0f; }
                else    { dk += (zz >= CMAX) ? 1.0f : -1.0f; }
            }
            warp_sum3(sv, cntf, dk);
            float tau = (sv + CMAX * dk - 1.0f) / fmaxf(cntf, 1.0f);
            if (t == 0) scal[1] = tau;
        }
        __syncthreads();

        // --- momentum update ---
        {
            float tn = 0.5f * (1.0f + sqrtf(1.0f + 4.0f * tf * tf));
            float tau = scal[1];
            float wn = clipc(vs[t] - tau);
            float yn = wn + ((tf - 1.0f) / tn) * (wn - wreg);
            wreg = wn;
            ys[t] = yn;
            ys2[t] = make_float2(yn, yn);
            tf = tn;
        }
        __syncthreads();
    }

    out[(size_t)b * NA + t] = wreg;
}

// ---------------------------------------------------------------------------
extern "C" void kernel_launch(void* const* d_in, const int* in_sizes, int n_in,
                              void* d_out, int out_size) {
    (void)in_sizes; (void)n_in; (void)out_size;
    const float* A = (const float*)d_in[0];
    float* out = (float*)d_out;

    const int dyn_smem = (5 * 4096 + 8 * NA) * sizeof(float);   // 90112 B
    cudaFuncSetAttribute(solver_kernel,
                         cudaFuncAttributeMaxDynamicSharedMemorySize, dyn_smem);

    qbuild_kernel<<<dim3(10, 1, NB), 256>>>(A);
    solver_kernel<<<NB, 256, dyn_smem>>>(out);
}

// round 15
// speedup vs baseline: 1.6980x; 1.1771x over previous
#include <cuda_runtime.h>

#define NA 256
#define NB 512
#define CMAX 0.05f
#define NITERS 300
#define PITERS 30
#define QUADROUNDS 3
#define NEWTONROUNDS 6

typedef unsigned long long ull;

// Upper-triangular Q blocks, fp32: 512 batches * 10 blocks * 64*64 floats = 82 MB
__device__ float g_Qs[(size_t)NB * 10 * 4096];

// gj-grouped order: (0,0) (0,1)(1,1) (0,2)(1,2)(2,2) (0,3)(1,3)(2,3)(3,3)
__constant__ int c_gi[10] = {0,0,1,0,1,2,0,1,2,3};
__constant__ int c_gj[10] = {0,1,1,2,2,2,3,3,3,3};

// ---------------------------------------------------------------------------
// Kernel 1: batched Q = A^T A, upper-triangular 64x64 tiles only.
// ---------------------------------------------------------------------------
__global__ __launch_bounds__(256) void qbuild_kernel(const float* __restrict__ A) {
    __shared__ float As[32][64];
    __shared__ float Bs[32][64];
    const int blk = blockIdx.x;
    const int b   = blockIdx.z;
    const int i0  = c_gi[blk] * 64;
    const int j0  = c_gj[blk] * 64;
    const float* Ab = A + (size_t)b * NA * NA;
    float*       Qb = g_Qs + ((size_t)b * 10 + blk) * 4096;
    const int t  = threadIdx.x;
    const int ty = t >> 4;
    const int tx = t & 15;

    float acc[4][4];
#pragma unroll
    for (int r = 0; r < 4; r++)
#pragma unroll
        for (int s = 0; s < 4; s++) acc[r][s] = 0.0f;

    for (int k0 = 0; k0 < NA; k0 += 32) {
        __syncthreads();
#pragma unroll
        for (int r = 0; r < 8; r++) {
            int idx = t + 256 * r;
            int kk = idx >> 6, c = idx & 63;
            As[kk][c] = Ab[(size_t)(k0 + kk) * NA + i0 + c];
            Bs[kk][c] = Ab[(size_t)(k0 + kk) * NA + j0 + c];
        }
        __syncthreads();
#pragma unroll
        for (int kk = 0; kk < 32; kk++) {
            float4 a4 = *(const float4*)&As[kk][ty * 4];
            float4 b4 = *(const float4*)&Bs[kk][tx * 4];
            float av[4] = {a4.x, a4.y, a4.z, a4.w};
            float bv[4] = {b4.x, b4.y, b4.z, b4.w};
#pragma unroll
            for (int r = 0; r < 4; r++)
#pragma unroll
                for (int s = 0; s < 4; s++)
                    acc[r][s] = fmaf(av[r], bv[s], acc[r][s]);
        }
    }
#pragma unroll
    for (int r = 0; r < 4; r++) {
        float4 o = make_float4(acc[r][0], acc[r][1], acc[r][2], acc[r][3]);
        *(float4*)&Qb[(ty * 4 + r) * 64 + tx * 4] = o;
    }
}

// ---------------------------------------------------------------------------
// Packed f32x2 helpers
// ---------------------------------------------------------------------------
__device__ __forceinline__ void ffma2u(ull& d, ull a, ull b) {
    asm("fma.rn.f32x2 %0, %1, %2, %0;" : "+l"(d) : "l"(a), "l"(b));
}
__device__ __forceinline__ void fadd2u(ull& d, ull a) {
    asm("add.rn.f32x2 %0, %0, %1;" : "+l"(d) : "l"(a));
}

__device__ __forceinline__ unsigned fkey(float x) {
    unsigned u = __float_as_uint(x);
    return u ^ (unsigned)(((int)u >> 31) | 0x80000000);
}
__device__ __forceinline__ float fkey_inv(unsigned k) {
    unsigned u = (k & 0x80000000u) ? (k ^ 0x80000000u) : ~k;
    return __uint_as_float(u);
}

__device__ __forceinline__ void warp_sum3(float& a, float& b, float& c) {
#pragma unroll
    for (int off = 16; off; off >>= 1) {
        a += __shfl_xor_sync(0xffffffffu, a, off);
        b += __shfl_xor_sync(0xffffffffu, b, off);
        c += __shfl_xor_sync(0xffffffffu, c, off);
    }
}
__device__ __forceinline__ void warp_sum2(float& a, float& b) {
#pragma unroll
    for (int off = 16; off; off >>= 1) {
        a += __shfl_xor_sync(0xffffffffu, a, off);
        b += __shfl_xor_sync(0xffffffffu, b, off);
    }
}
__device__ __forceinline__ float warp_sum(float v) {
#pragma unroll
    for (int off = 16; off; off >>= 1)
        v += __shfl_xor_sync(0xffffffffu, v, off);
    return v;
}
__device__ __forceinline__ float clipc(float z) {
    return fminf(fmaxf(z, -CMAX), CMAX);
}

// ---------------------------------------------------------------------------
// Kernel 2: per-batch solver, 256 threads, 2 CTAs/SM.
// Thread (ty=t>>3 in 0..31, tx=t&7) owns rows {ty, ty+32} and columns
// {4tx..4tx+3} U {32+4tx..32+4tx+3} of each block (split-half mapping:
// each quarter-warp's 16B LDS cover 128 consecutive bytes -> conflict-free).
// Blocks 0..4 register-resident, blocks 5..9 in smem.
// ---------------------------------------------------------------------------
__global__ __launch_bounds__(256, 2) void solver_kernel(float* __restrict__ out) {
    extern __shared__ __align__(16) float sdyn[];   // Qsm[5*4096] + red[8*256]
    float* Qsm = sdyn;
    float* red = sdyn + 5 * 4096;
    __shared__ __align__(16) float  ys[NA];
    __shared__ __align__(16) float2 ys2[NA];        // (y,y) duplicated pairs
    __shared__ __align__(16) float  vs[NA];
    __shared__ __align__(16) float  rowsum[NA];
    __shared__ float scal[2];

    const int b  = blockIdx.x;
    const int t  = threadIdx.x;
    const int ty = t >> 3;          // 0..31
    const int tx = t & 7;           // 0..7
    const int w  = t >> 5;          // warp 0..7
    const float* Qb = g_Qs + (size_t)b * 10 * 4096;

    // ---- register half: blocks 0..4, rows {ty, ty+32}, split cols ----
    ull qq[5][2][4];
#pragma unroll
    for (int q = 0; q < 5; q++)
#pragma unroll
        for (int k = 0; k < 2; k++) {
            const float* src = Qb + q * 4096 + (ty + 32 * k) * 64;
            ulonglong2 u0 = *(const ulonglong2*)(src + 4 * tx);
            ulonglong2 u1 = *(const ulonglong2*)(src + 32 + 4 * tx);
            qq[q][k][0] = u0.x; qq[q][k][1] = u0.y;
            qq[q][k][2] = u1.x; qq[q][k][3] = u1.y;
        }
    // ---- smem half: blocks 5..9 copied verbatim ----
    {
        const float4* src = (const float4*)(Qb + 5 * 4096);
        float4* dst = (float4*)Qsm;
        for (int i = t; i < 5 * 1024; i += 256) dst[i] = src[i];
    }
    ys[t] = 0.0625f;
    ys2[t] = make_float2(0.0625f, 0.0625f);
    rowsum[t] = 0.0f;
    __syncthreads();

    // ---- symv: z[t] = (Q y)[t], symmetry-exploiting ----
    auto symv = [&]() -> float {
        ull racc[3][2];
#pragma unroll
        for (int gi = 0; gi < 3; gi++)
#pragma unroll
            for (int k = 0; k < 2; k++) racc[gi][k] = 0ull;

        int qidx = 0;
#pragma unroll
        for (int gj = 0; gj < 4; gj++) {
            ull cacc[4] = {0ull, 0ull, 0ull, 0ull};
            ull yj[4];
            {
                ulonglong2 u0 = *(const ulonglong2*)&ys[gj * 64 + 4 * tx];
                ulonglong2 u1 = *(const ulonglong2*)&ys[gj * 64 + 32 + 4 * tx];
                yj[0] = u0.x; yj[1] = u0.y; yj[2] = u1.x; yj[3] = u1.y;
            }
#pragma unroll
            for (int gi = 0; gi <= gj; gi++) {
                ull q0[4], q1[4];
                if (qidx < 5) {
#pragma unroll
                    for (int c = 0; c < 4; c++) { q0[c] = qq[qidx][0][c]; q1[c] = qq[qidx][1][c]; }
                } else {
                    const float* srow = Qsm + (qidx - 5) * 4096 + ty * 64;
                    ulonglong2 a0 = *(const ulonglong2*)(srow + 4 * tx);
                    ulonglong2 a1 = *(const ulonglong2*)(srow + 32 + 4 * tx);
                    ulonglong2 b0 = *(const ulonglong2*)(srow + 32 * 64 + 4 * tx);
                    ulonglong2 b1 = *(const ulonglong2*)(srow + 32 * 64 + 32 + 4 * tx);
                    q0[0] = a0.x; q0[1] = a0.y; q0[2] = a1.x; q0[3] = a1.y;
                    q1[0] = b0.x; q1[1] = b0.y; q1[2] = b1.x; q1[3] = b1.y;
                }
                ull yi0 = *(const ull*)&ys2[gi * 64 + ty];
                ull yi1 = *(const ull*)&ys2[gi * 64 + ty + 32];
#pragma unroll
                for (int c = 0; c < 4; c++) {
                    ffma2u(cacc[c], q0[c], yi0);
                    ffma2u(cacc[c], q1[c], yi1);
                }
                if (gi != gj) {
#pragma unroll
                    for (int c = 0; c < 4; c++) {
                        ffma2u(racc[gi][0], q0[c], yj[c]);
                        ffma2u(racc[gi][1], q1[c], yj[c]);
                    }
                }
                qidx++;
            }
            // reduce cacc over the 4 ty-subgroups within the warp
#pragma unroll
            for (int c = 0; c < 4; c++) {
                ull o8  = __shfl_xor_sync(0xffffffffu, cacc[c], 8);
                fadd2u(cacc[c], o8);
                ull o16 = __shfl_xor_sync(0xffffffffu, cacc[c], 16);
                fadd2u(cacc[c], o16);
            }
            if ((ty & 3) == 0) {
                *(ulonglong2*)&red[w * NA + gj * 64 + 4 * tx]      = make_ulonglong2(cacc[0], cacc[1]);
                *(ulonglong2*)&red[w * NA + gj * 64 + 32 + 4 * tx] = make_ulonglong2(cacc[2], cacc[3]);
            }
        }

        // row path: horizontal add then reduce over the 8 tx lanes
#pragma unroll
        for (int gi = 0; gi < 3; gi++)
#pragma unroll
            for (int k = 0; k < 2; k++) {
                float2 rp = *(float2*)&racc[gi][k];
                float v = rp.x + rp.y;
                v += __shfl_xor_sync(0xffffffffu, v, 1);
                v += __shfl_xor_sync(0xffffffffu, v, 2);
                v += __shfl_xor_sync(0xffffffffu, v, 4);
                if (tx == 0) rowsum[gi * 64 + ty + 32 * k] += v;
            }
        __syncthreads();

        float z = rowsum[t];
#pragma unroll
        for (int q = 0; q < 8; q++) z += red[q * NA + t];
        rowsum[t] = 0.0f;   // reset own slot; caller barriers before next symv
        return z;
    };

    // ---------------- power iteration for lambda_max ----------------
    for (int it = 0; it < PITERS; it++) {
        float z = symv();
        vs[t] = z;
        __syncthreads();
        if (t < 32) {
            float zr[8];
            float ss = 0.0f;
#pragma unroll
            for (int k = 0; k < 8; k++) { zr[k] = vs[t + 32 * k]; ss = fmaf(zr[k], zr[k], ss); }
            ss = warp_sum(ss);
            float inv = 1.0f / (sqrtf(ss) + 1e-12f);
#pragma unroll
            for (int k = 0; k < 8; k++) {
                float yv = zr[k] * inv;
                ys[t + 32 * k] = yv;
                ys2[t + 32 * k] = make_float2(yv, yv);
            }
        }
        __syncthreads();
    }
    {
        float z = symv();
        vs[t] = z;
        __syncthreads();
        if (t < 32) {
            float ss = 0.0f;
#pragma unroll
            for (int k = 0; k < 8; k++) ss = fmaf(ys[t + 32 * k], vs[t + 32 * k], ss);
            ss = warp_sum(ss);
            if (t == 0) scal[0] = 1.0f / (2.0f * ss + 1e-12f);
        }
        __syncthreads();
    }
    const float step = scal[0];

    // ---------------- FISTA ----------------
    float wreg = 1.0f / 256.0f;
    float tf = 1.0f;
    ys[t] = wreg;
    ys2[t] = make_float2(wreg, wreg);
    __syncthreads();

    for (int it = 0; it < NITERS; it++) {
        float z = symv();
        vs[t] = ys[t] - step * (2.0f * z);
        __syncthreads();

        // --- projection on WARP 0 ONLY (proven recipe) ---
        if (t < 32) {
            float vr[8];
#pragma unroll
            for (int k = 0; k < 8; k++) vr[k] = vs[t + 32 * k];

            float mn = vr[0], mx = vr[0];
#pragma unroll
            for (int k = 1; k < 8; k++) { mn = fminf(mn, vr[k]); mx = fmaxf(mx, vr[k]); }
            unsigned kmn = __reduce_min_sync(0xffffffffu, fkey(mn));
            unsigned kmx = __reduce_max_sync(0xffffffffu, fkey(mx));
            float lo = fkey_inv(kmn) - CMAX;
            float hi = fkey_inv(kmx) + CMAX;

            for (int r = 0; r < QUADROUNDS; r++) {
                float d  = hi - lo;
                float m1 = lo + 0.25f * d;
                float m2 = lo + 0.50f * d;
                float m3 = lo + 0.75f * d;
                float s1 = 0.0f, s2 = 0.0f, s3 = 0.0f;
#pragma unroll
                for (int k = 0; k < 8; k++) {
                    s1 += clipc(vr[k] - m1);
                    s2 += clipc(vr[k] - m2);
                    s3 += clipc(vr[k] - m3);
                }
                warp_sum3(s1, s2, s3);
                if (s2 > 1.0f) {
                    bool p3 = s3 > 1.0f;
                    lo = p3 ? m3 : m2;
                    hi = p3 ? hi : m3;
                } else {
                    bool p1 = s1 > 1.0f;
                    lo = p1 ? m1 : lo;
                    hi = p1 ? m2 : m1;
                }
            }
            float tau0 = 0.5f * (lo + hi);
            for (int r = 0; r < NEWTONROUNDS; r++) {
                float s = 0.0f, cnt = 0.0f;
#pragma unroll
                for (int k = 0; k < 8; k++) {
                    float zz = vr[k] - tau0;
                    s += clipc(zz);
                    cnt += (fabsf(zz) < CMAX) ? 1.0f : 0.0f;
                }
                warp_sum2(s, cnt);
                bool p = s > 1.0f;
                lo = p ? tau0 : lo;
                hi = p ? hi : tau0;
                float nt = tau0 + (s - 1.0f) / fmaxf(cnt, 1.0f);
                tau0 = (nt > lo && nt < hi) ? nt : 0.5f * (lo + hi);
            }

            float sv = 0.0f, cntf = 0.0f, dk = 0.0f;
#pragma unroll
            for (int k = 0; k < 8; k++) {
                float zz = vr[k] - tau0;
                bool in = fabsf(zz) < CMAX;
                if (in) { sv += vr[k]; cntf += 1.0f; }
                else    { dk += (zz >= CMAX) ? 1.0f : -1.0f; }
            }
            warp_sum3(sv, cntf, dk);
            float tau = (sv + CMAX * dk - 1.0f) / fmaxf(cntf, 1.0f);
            if (t == 0) scal[1] = tau;
        }
        __syncthreads();

        // --- momentum update ---
        {
            float tn = 0.5f * (1.0f + sqrtf(1.0f + 4.0f * tf * tf));
            float tau = scal[1];
            float wn = clipc(vs[t] - tau);
            float yn = wn + ((tf - 1.0f) / tn) * (wn - wreg);
            wreg = wn;
            ys[t] = yn;
            ys2[t] = make_float2(yn, yn);
            tf = tn;
        }
        __syncthreads();
    }

    out[(size_t)b * NA + t] = wreg;
}

// ---------------------------------------------------------------------------
extern "C" void kernel_launch(void* const* d_in, const int* in_sizes, int n_in,
                              void* d_out, int out_size) {
    (void)in_sizes; (void)n_in; (void)out_size;
    const float* A = (const float*)d_in[0];
    float* out = (float*)d_out;

    const int dyn_smem = (5 * 4096 + 8 * NA) * sizeof(float);   // 90112 B
    cudaFuncSetAttribute(solver_kernel,
                         cudaFuncAttributeMaxDynamicSharedMemorySize, dyn_smem);

    qbuild_kernel<<<dim3(10, 1, NB), 256>>>(A);
    solver_kernel<<<NB, 256, dyn_smem>>>(out);
}

// round 16
// speedup vs baseline: 1.9280x; 1.1354x over previous
#include <cuda_runtime.h>

#define NA 256
#define NB 512
#define CMAX 0.05f
#define NITERS 300
#define PITERS 30
#define QUADROUNDS 3
#define NEWTONROUNDS 6

typedef unsigned long long ull;

// Upper-triangular Q blocks, fp32: 512 batches * 10 blocks * 64*64 floats = 82 MB
__device__ float g_Qs[(size_t)NB * 10 * 4096];

// gj-grouped order: (0,0) (0,1)(1,1) (0,2)(1,2)(2,2) (0,3)(1,3)(2,3)(3,3)
__constant__ int c_gi[10] = {0,0,1,0,1,2,0,1,2,3};
__constant__ int c_gj[10] = {0,1,1,2,2,2,3,3,3,3};

// ---------------------------------------------------------------------------
// Kernel 1: batched Q = A^T A, upper-triangular 64x64 tiles only.
// ---------------------------------------------------------------------------
__global__ __launch_bounds__(256) void qbuild_kernel(const float* __restrict__ A) {
    __shared__ float As[32][64];
    __shared__ float Bs[32][64];
    const int blk = blockIdx.x;
    const int b   = blockIdx.z;
    const int i0  = c_gi[blk] * 64;
    const int j0  = c_gj[blk] * 64;
    const float* Ab = A + (size_t)b * NA * NA;
    float*       Qb = g_Qs + ((size_t)b * 10 + blk) * 4096;
    const int t  = threadIdx.x;
    const int ty = t >> 4;
    const int tx = t & 15;

    float acc[4][4];
#pragma unroll
    for (int r = 0; r < 4; r++)
#pragma unroll
        for (int s = 0; s < 4; s++) acc[r][s] = 0.0f;

    for (int k0 = 0; k0 < NA; k0 += 32) {
        __syncthreads();
#pragma unroll
        for (int r = 0; r < 8; r++) {
            int idx = t + 256 * r;
            int kk = idx >> 6, c = idx & 63;
            As[kk][c] = Ab[(size_t)(k0 + kk) * NA + i0 + c];
            Bs[kk][c] = Ab[(size_t)(k0 + kk) * NA + j0 + c];
        }
        __syncthreads();
#pragma unroll
        for (int kk = 0; kk < 32; kk++) {
            float4 a4 = *(const float4*)&As[kk][ty * 4];
            float4 b4 = *(const float4*)&Bs[kk][tx * 4];
            float av[4] = {a4.x, a4.y, a4.z, a4.w};
            float bv[4] = {b4.x, b4.y, b4.z, b4.w};
#pragma unroll
            for (int r = 0; r < 4; r++)
#pragma unroll
                for (int s = 0; s < 4; s++)
                    acc[r][s] = fmaf(av[r], bv[s], acc[r][s]);
        }
    }
#pragma unroll
    for (int r = 0; r < 4; r++) {
        float4 o = make_float4(acc[r][0], acc[r][1], acc[r][2], acc[r][3]);
        *(float4*)&Qb[(ty * 4 + r) * 64 + tx * 4] = o;
    }
}

// ---------------------------------------------------------------------------
// Packed f32x2 helpers
// ---------------------------------------------------------------------------
__device__ __forceinline__ void ffma2u(ull& d, ull a, ull b) {
    asm("fma.rn.f32x2 %0, %1, %2, %0;" : "+l"(d) : "l"(a), "l"(b));
}
__device__ __forceinline__ void fadd2u(ull& d, ull a) {
    asm("add.rn.f32x2 %0, %0, %1;" : "+l"(d) : "l"(a));
}

__device__ __forceinline__ unsigned fkey(float x) {
    unsigned u = __float_as_uint(x);
    return u ^ (unsigned)(((int)u >> 31) | 0x80000000);
}
__device__ __forceinline__ float fkey_inv(unsigned k) {
    unsigned u = (k & 0x80000000u) ? (k ^ 0x80000000u) : ~k;
    return __uint_as_float(u);
}

// fixed-point warp sum via REDUX (scale 2^20)
#define FXS 1048576.0f
#define FXI 9.5367431640625e-7f
__device__ __forceinline__ float redux_fsum(float x) {
    int xi = __float2int_rn(x * FXS);
    xi = __reduce_add_sync(0xffffffffu, xi);
    return (float)xi * FXI;
}

__device__ __forceinline__ float warp_sum(float v) {
#pragma unroll
    for (int off = 16; off; off >>= 1)
        v += __shfl_xor_sync(0xffffffffu, v, off);
    return v;
}
__device__ __forceinline__ float clipc(float z) {
    return fminf(fmaxf(z, -CMAX), CMAX);
}

// ---------------------------------------------------------------------------
// Kernel 2: per-batch solver, 256 threads, 2 CTAs/SM.
// Thread (ty=t>>3, tx=t&7) owns rows {ty, ty+32}, cols {4tx..4tx+3} U
// {32+4tx..32+4tx+3} per block (conflict-free LDS).  Blocks 0..4 in regs,
// 5..9 in smem.  FISTA scalar state + w lives in warp 0's registers.
// ---------------------------------------------------------------------------
__global__ __launch_bounds__(256, 2) void solver_kernel(float* __restrict__ out) {
    extern __shared__ __align__(16) float sdyn[];   // Qsm[5*4096] + red[8*256]
    float* Qsm = sdyn;
    float* red = sdyn + 5 * 4096;
    __shared__ __align__(16) float  ys[NA];
    __shared__ __align__(16) float2 ys2[NA];        // (y,y) duplicated pairs
    __shared__ __align__(16) float  vs[NA];
    __shared__ __align__(16) float  rowsum[NA];
    __shared__ float scal[2];

    const int b  = blockIdx.x;
    const int t  = threadIdx.x;
    const int ty = t >> 3;          // 0..31
    const int tx = t & 7;           // 0..7
    const int w  = t >> 5;          // warp 0..7
    const float* Qb = g_Qs + (size_t)b * 10 * 4096;

    // ---- register half: blocks 0..4, rows {ty, ty+32}, split cols ----
    ull qq[5][2][4];
#pragma unroll
    for (int q = 0; q < 5; q++)
#pragma unroll
        for (int k = 0; k < 2; k++) {
            const float* src = Qb + q * 4096 + (ty + 32 * k) * 64;
            ulonglong2 u0 = *(const ulonglong2*)(src + 4 * tx);
            ulonglong2 u1 = *(const ulonglong2*)(src + 32 + 4 * tx);
            qq[q][k][0] = u0.x; qq[q][k][1] = u0.y;
            qq[q][k][2] = u1.x; qq[q][k][3] = u1.y;
        }
    // ---- smem half: blocks 5..9 copied verbatim ----
    {
        const float4* src = (const float4*)(Qb + 5 * 4096);
        float4* dst = (float4*)Qsm;
        for (int i = t; i < 5 * 1024; i += 256) dst[i] = src[i];
    }
    ys[t] = 0.0625f;
    ys2[t] = make_float2(0.0625f, 0.0625f);
    rowsum[t] = 0.0f;
    __syncthreads();

    // ---- symv: z[t] = (Q y)[t], symmetry-exploiting ----
    auto symv = [&]() -> float {
        ull racc[3][2];
#pragma unroll
        for (int gi = 0; gi < 3; gi++)
#pragma unroll
            for (int k = 0; k < 2; k++) racc[gi][k] = 0ull;

        int qidx = 0;
#pragma unroll
        for (int gj = 0; gj < 4; gj++) {
            ull cacc[4] = {0ull, 0ull, 0ull, 0ull};
            ull yj[4];
            {
                ulonglong2 u0 = *(const ulonglong2*)&ys[gj * 64 + 4 * tx];
                ulonglong2 u1 = *(const ulonglong2*)&ys[gj * 64 + 32 + 4 * tx];
                yj[0] = u0.x; yj[1] = u0.y; yj[2] = u1.x; yj[3] = u1.y;
            }
#pragma unroll
            for (int gi = 0; gi <= gj; gi++) {
                ull q0[4], q1[4];
                if (qidx < 5) {
#pragma unroll
                    for (int c = 0; c < 4; c++) { q0[c] = qq[qidx][0][c]; q1[c] = qq[qidx][1][c]; }
                } else {
                    const float* srow = Qsm + (qidx - 5) * 4096 + ty * 64;
                    ulonglong2 a0 = *(const ulonglong2*)(srow + 4 * tx);
                    ulonglong2 a1 = *(const ulonglong2*)(srow + 32 + 4 * tx);
                    ulonglong2 b0 = *(const ulonglong2*)(srow + 32 * 64 + 4 * tx);
                    ulonglong2 b1 = *(const ulonglong2*)(srow + 32 * 64 + 32 + 4 * tx);
                    q0[0] = a0.x; q0[1] = a0.y; q0[2] = a1.x; q0[3] = a1.y;
                    q1[0] = b0.x; q1[1] = b0.y; q1[2] = b1.x; q1[3] = b1.y;
                }
                ull yi0 = *(const ull*)&ys2[gi * 64 + ty];
                ull yi1 = *(const ull*)&ys2[gi * 64 + ty + 32];
#pragma unroll
                for (int c = 0; c < 4; c++) {
                    ffma2u(cacc[c], q0[c], yi0);
                    ffma2u(cacc[c], q1[c], yi1);
                }
                if (gi != gj) {
#pragma unroll
                    for (int c = 0; c < 4; c++) {
                        ffma2u(racc[gi][0], q0[c], yj[c]);
                        ffma2u(racc[gi][1], q1[c], yj[c]);
                    }
                }
                qidx++;
            }
            // reduce cacc over the 4 ty-subgroups within the warp
#pragma unroll
            for (int c = 0; c < 4; c++) {
                ull o8  = __shfl_xor_sync(0xffffffffu, cacc[c], 8);
                fadd2u(cacc[c], o8);
                ull o16 = __shfl_xor_sync(0xffffffffu, cacc[c], 16);
                fadd2u(cacc[c], o16);
            }
            if ((ty & 3) == 0) {
                *(ulonglong2*)&red[w * NA + gj * 64 + 4 * tx]      = make_ulonglong2(cacc[0], cacc[1]);
                *(ulonglong2*)&red[w * NA + gj * 64 + 32 + 4 * tx] = make_ulonglong2(cacc[2], cacc[3]);
            }
        }

        // row path: horizontal add then reduce over the 8 tx lanes
#pragma unroll
        for (int gi = 0; gi < 3; gi++)
#pragma unroll
            for (int k = 0; k < 2; k++) {
                float2 rp = *(float2*)&racc[gi][k];
                float v = rp.x + rp.y;
                v += __shfl_xor_sync(0xffffffffu, v, 1);
                v += __shfl_xor_sync(0xffffffffu, v, 2);
                v += __shfl_xor_sync(0xffffffffu, v, 4);
                if (tx == 0) rowsum[gi * 64 + ty + 32 * k] += v;
            }
        __syncthreads();

        float z = rowsum[t];
#pragma unroll
        for (int q = 0; q < 8; q++) z += red[q * NA + t];
        rowsum[t] = 0.0f;   // reset own slot; caller barriers before next symv
        return z;
    };

    // ---------------- power iteration for lambda_max ----------------
    for (int it = 0; it < PITERS; it++) {
        float z = symv();
        vs[t] = z;
        __syncthreads();
        if (t < 32) {
            float zr[8];
            float ss = 0.0f;
#pragma unroll
            for (int k = 0; k < 8; k++) { zr[k] = vs[t + 32 * k]; ss = fmaf(zr[k], zr[k], ss); }
            ss = warp_sum(ss);
            float inv = 1.0f / (sqrtf(ss) + 1e-12f);
#pragma unroll
            for (int k = 0; k < 8; k++) {
                float yv = zr[k] * inv;
                ys[t + 32 * k] = yv;
                ys2[t + 32 * k] = make_float2(yv, yv);
            }
        }
        __syncthreads();
    }
    {
        float z = symv();
        vs[t] = z;
        __syncthreads();
        if (t < 32) {
            float ss = 0.0f;
#pragma unroll
            for (int k = 0; k < 8; k++) ss = fmaf(ys[t + 32 * k], vs[t + 32 * k], ss);
            ss = warp_sum(ss);
            if (t == 0) scal[0] = 1.0f / (2.0f * ss + 1e-12f);
        }
        __syncthreads();
    }
    const float step = scal[0];

    // ---------------- FISTA ----------------
    // w state lives in warp 0's registers (wr[k] = w[t + 32k])
    float wr[8];
#pragma unroll
    for (int k = 0; k < 8; k++) wr[k] = 1.0f / 256.0f;
    float tf = 1.0f;
    ys[t] = 1.0f / 256.0f;
    ys2[t] = make_float2(1.0f / 256.0f, 1.0f / 256.0f);
    __syncthreads();

    for (int it = 0; it < NITERS; it++) {
        float z = symv();
        vs[t] = ys[t] - step * (2.0f * z);
        __syncthreads();

        // --- projection + momentum update, WARP 0 ONLY, REDUX reductions ---
        if (t < 32) {
            float vr[8];
#pragma unroll
            for (int k = 0; k < 8; k++) vr[k] = vs[t + 32 * k];

            float mn = vr[0], mx = vr[0];
#pragma unroll
            for (int k = 1; k < 8; k++) { mn = fminf(mn, vr[k]); mx = fmaxf(mx, vr[k]); }
            unsigned kmn = __reduce_min_sync(0xffffffffu, fkey(mn));
            unsigned kmx = __reduce_max_sync(0xffffffffu, fkey(mx));
            float lo = fkey_inv(kmn) - CMAX;
            float hi = fkey_inv(kmx) + CMAX;

            // 3 quartile rounds (64x bracket shrink)
            for (int r = 0; r < QUADROUNDS; r++) {
                float d  = hi - lo;
                float m1 = lo + 0.25f * d;
                float m2 = lo + 0.50f * d;
                float m3 = lo + 0.75f * d;
                float s1 = 0.0f, s2 = 0.0f, s3 = 0.0f;
#pragma unroll
                for (int k = 0; k < 8; k++) {
                    s1 += clipc(vr[k] - m1);
                    s2 += clipc(vr[k] - m2);
                    s3 += clipc(vr[k] - m3);
                }
                s1 = redux_fsum(s1);
                s2 = redux_fsum(s2);
                s3 = redux_fsum(s3);
                if (s2 > 1.0f) {
                    bool p3 = s3 > 1.0f;
                    lo = p3 ? m3 : m2;
                    hi = p3 ? hi : m3;
                } else {
                    bool p1 = s1 > 1.0f;
                    lo = p1 ? m1 : lo;
                    hi = p1 ? m2 : m1;
                }
            }
            float tau0 = 0.5f * (lo + hi);
            // safeguarded Newton
            for (int r = 0; r < NEWTONROUNDS; r++) {
                float s = 0.0f;
                int cnt = 0;
#pragma unroll
                for (int k = 0; k < 8; k++) {
                    float zz = vr[k] - tau0;
                    s += clipc(zz);
                    cnt += (fabsf(zz) < CMAX) ? 1 : 0;
                }
                s = redux_fsum(s);
                cnt = __reduce_add_sync(0xffffffffu, cnt);
                bool p = s > 1.0f;
                lo = p ? tau0 : lo;
                hi = p ? hi : tau0;
                float nt = tau0 + (s - 1.0f) / fmaxf((float)cnt, 1.0f);
                tau0 = (nt > lo && nt < hi) ? nt : 0.5f * (lo + hi);
            }

            // exact tau from active set (matches reference recompute)
            float sv = 0.0f;
            int cnt = 0, dk = 0;
#pragma unroll
            for (int k = 0; k < 8; k++) {
                float zz = vr[k] - tau0;
                bool in = fabsf(zz) < CMAX;
                if (in) { sv += vr[k]; cnt += 1; }
                else    { dk += (zz >= CMAX) ? 1 : -1; }
            }
            sv = redux_fsum(sv);
            cnt = __reduce_add_sync(0xffffffffu, cnt);
            dk  = __reduce_add_sync(0xffffffffu, dk);
            float tau = (sv + CMAX * (float)dk - 1.0f) / fmaxf((float)cnt, 1.0f);

            // fused momentum update from warp-0 registers
            float tn = 0.5f * (1.0f + sqrtf(1.0f + 4.0f * tf * tf));
            float mom = (tf - 1.0f) / tn;
#pragma unroll
            for (int k = 0; k < 8; k++) {
                float wn = clipc(vr[k] - tau);
                float yn = wn + mom * (wn - wr[k]);
                wr[k] = wn;
                ys[t + 32 * k] = yn;
                ys2[t + 32 * k] = make_float2(yn, yn);
            }
            tf = tn;
        }
        __syncthreads();
    }

    if (t < 32) {
#pragma unroll
        for (int k = 0; k < 8; k++)
            out[(size_t)b * NA + t + 32 * k] = wr[k];
    }
}

// ---------------------------------------------------------------------------
extern "C" void kernel_launch(void* const* d_in, const int* in_sizes, int n_in,
                              void* d_out, int out_size) {
    (void)in_sizes; (void)n_in; (void)out_size;
    const float* A = (const float*)d_in[0];
    float* out = (float*)d_out;

    const int dyn_smem = (5 * 4096 + 8 * NA) * sizeof(float);   // 90112 B
    cudaFuncSetAttribute(solver_kernel,
                         cudaFuncAttributeMaxDynamicSharedMemorySize, dyn_smem);

    qbuild_kernel<<<dim3(10, 1, NB), 256>>>(A);
    solver_kernel<<<NB, 256, dyn_smem>>>(out);
}